// round 2
// baseline (speedup 1.0000x reference)
#include <cuda_runtime.h>

// DihedralToCartesian: B=65536 independent chains, N=126 sequential extension steps.
// Thread = one batch. CTA = 128 consecutive batches. Angle tiles and output tiles
// staged through shared memory for coalesced global traffic.
// R2: CHUNK 18->9 and __launch_bounds__(128,6) to lift occupancy (R1: 255 regs, occ 11%).

#define TPB      128
#define NRES     126
#define CHUNK    9             // divisible by 3 -> alpha/bond constants compile-time
#define NCHUNK   (NRES / CHUNK)
#define SIN_PITCH 11           // gcd(11,32)=1 -> conflict-free per-thread row reads
#define OUT_PITCH 29           // 9*3=27 payload, pad to 29 (gcd(29,32)=1)

__device__ __forceinline__ float frsqrt(float x) {
    float y;
    asm("rsqrt.approx.f32 %0, %1;" : "=f"(y) : "f"(x));
    return y;
}

__global__ void __launch_bounds__(TPB, 6)
dihedral_kernel(const float* __restrict__ angles,
                const float* __restrict__ prev,
                float* __restrict__ out)
{
    __shared__ float s_sin[TPB * SIN_PITCH];
    __shared__ float s_cos[TPB * SIN_PITCH];
    __shared__ float s_out[TPB * OUT_PITCH];

    const int tid   = threadIdx.x;
    const int Bbase = blockIdx.x * TPB;

    // rotation constants: rot0 = bond*cos(alpha), rs = bond*sin(alpha), period 3
    float R0[3], RS[3];
    {
        const float alpha[3] = {2.028f, 2.124f, 1.941f};
        const float bond [3] = {1.329f, 1.458f, 1.523f};
        #pragma unroll
        for (int k = 0; k < 3; ++k) {
            R0[k] = bond[k] * cosf(alpha[k]);
            RS[k] = bond[k] * sinf(alpha[k]);
        }
    }

    // carry (a, b, c) from prev_three[b, 0..2, :]
    const float* p = prev + (size_t)(Bbase + tid) * 9;
    float ax = p[0], ay = p[1], az = p[2];
    float bx = p[3], by = p[4], bz = p[5];
    float cx = p[6], cy = p[7], cz = p[8];

    const float* gang = angles + (size_t)Bbase * (2 * NRES);
    float*       gout = out    + (size_t)Bbase * (NRES * 3);

    for (int ch = 0; ch < NCHUNK; ++ch) {
        const int i0 = ch * CHUNK;

        // ---- cooperative coalesced load of sin/cos tiles ----
        #pragma unroll
        for (int e = tid; e < TPB * CHUNK; e += TPB) {
            int r = e / CHUNK;
            int q = e - r * CHUNK;
            s_sin[r * SIN_PITCH + q] = gang[r * (2 * NRES) + i0 + q];
            s_cos[r * SIN_PITCH + q] = gang[r * (2 * NRES) + NRES + i0 + q];
        }
        __syncthreads();

        // ---- CHUNK sequential extension steps ----
        const float* ms = &s_sin[tid * SIN_PITCH];
        const float* mc = &s_cos[tid * SIN_PITCH];
        float*       mo = &s_out[tid * OUT_PITCH];

        #pragma unroll
        for (int j = 0; j < CHUNK; ++j) {
            const int k = j % 3;   // compile-time under full unroll (i0 % 3 == 0)
            float s  = ms[j];
            float co = mc[j];

            // normalize (sin, cos): n = sqrt(s^2 + c^2 + 1e-8)
            float invn = frsqrt(fmaf(s, s, fmaf(co, co, 1e-8f)));
            float t    = RS[k] * invn;
            float rot0 = R0[k];
            float rot1 =  t * co;
            float rot2 = -t * s;

            // bc = normalize((b - c) + 1e-8)
            float bcx = (bx - cx) + 1e-8f;
            float bcy = (by - cy) + 1e-8f;
            float bcz = (bz - cz) + 1e-8f;
            float ib = frsqrt(fmaf(bcx, bcx, fmaf(bcy, bcy, bcz * bcz)));
            bcx *= ib; bcy *= ib; bcz *= ib;

            // n = normalize(cross(b - a, bc) + 1e-8)
            float vx = bx - ax, vy = by - ay, vz = bz - az;
            float nx = fmaf(vy, bcz, fmaf(-vz, bcy, 1e-8f));
            float ny = fmaf(vz, bcx, fmaf(-vx, bcz, 1e-8f));
            float nz = fmaf(vx, bcy, fmaf(-vy, bcx, 1e-8f));
            float in_ = frsqrt(fmaf(nx, nx, fmaf(ny, ny, nz * nz)));
            nx *= in_; ny *= in_; nz *= in_;

            // m1 = cross(n, bc)
            float mx = ny * bcz - nz * bcy;
            float my = nz * bcx - nx * bcz;
            float mz = nx * bcy - ny * bcx;

            // d = c + rot0*bc + rot1*m1 + rot2*n
            float dx = fmaf(rot2, nx, fmaf(rot1, mx, fmaf(rot0, bcx, cx)));
            float dy = fmaf(rot2, ny, fmaf(rot1, my, fmaf(rot0, bcy, cy)));
            float dz = fmaf(rot2, nz, fmaf(rot1, mz, fmaf(rot0, bcz, cz)));

            mo[j * 3 + 0] = dx;
            mo[j * 3 + 1] = dy;
            mo[j * 3 + 2] = dz;

            // shift carry
            ax = bx; ay = by; az = bz;
            bx = cx; by = cy; bz = cz;
            cx = dx; cy = dy; cz = dz;
        }
        __syncthreads();

        // ---- cooperative coalesced store of output tile ----
        #pragma unroll
        for (int e = tid; e < TPB * CHUNK * 3; e += TPB) {
            int r = e / (CHUNK * 3);
            int q = e - r * (CHUNK * 3);
            gout[r * (NRES * 3) + i0 * 3 + q] = s_out[r * OUT_PITCH + q];
        }
        __syncthreads();
    }
}

extern "C" void kernel_launch(void* const* d_in, const int* in_sizes, int n_in,
                              void* d_out, int out_size)
{
    const float* angles = (const float*)d_in[0];   // (B, 252) f32
    const float* prev   = (const float*)d_in[1];   // (B, 3, 3) f32
    float*       out    = (float*)d_out;           // (B, 126, 3) f32

    const int B = in_sizes[0] / (2 * NRES);        // 65536
    dihedral_kernel<<<B / TPB, TPB>>>(angles, prev, out);
}

// round 4
// speedup vs baseline: 1.2326x; 1.2326x over previous
#include <cuda_runtime.h>

// DihedralToCartesian R4: algebraically simplified, numerically exact recurrence.
// Carry p (last point), w = unit(last bond dir), v = unit(prev bond dir).
// Steady step i (>=1):
//   bc = -w                        (reference's normalize(b-c) cancels algebraically)
//   n  = unit(cross(w, v))         (= reference's unit(cross(b-a, bc)), scale factors > 0 drop)
//   m1 = cross(w, n)               (= cross(n, bc))
//   u  = -cos_a*w + sin_a*cos_t*m1 - sin_a*sin_t*n
//   p += bond*u ;  v = w ;  w = u/|u|   (true rsqrt each step -> self-correcting, no drift)
// Step 0 (raw prev_three geometry) is peeled and reference-faithful.

#define TPB      64
#define NRES     126
#define CHUNK    9             // divisible by 3 -> constants compile-time
#define NCHUNK   (NRES / CHUNK)
#define SIN_PITCH 11           // gcd(11,32)=1 -> conflict-free per-thread rows
#define OUT_PITCH 29           // 27 payload + pad, gcd(29,32)=1

__device__ __forceinline__ float frsqrt(float x) {
    float y;
    asm("rsqrt.approx.f32 %0, %1;" : "=f"(y) : "f"(x));
    return y;
}

__global__ void __launch_bounds__(TPB, 8)
dihedral_kernel(const float* __restrict__ angles,
                const float* __restrict__ prev,
                float* __restrict__ out)
{
    __shared__ float s_sin[TPB * SIN_PITCH];
    __shared__ float s_cos[TPB * SIN_PITCH];
    __shared__ float s_out[TPB * OUT_PITCH];

    const int tid   = threadIdx.x;
    const int Bbase = blockIdx.x * TPB;

    float CA[3], SA[3], BOND[3];
    {
        const float alpha[3] = {2.028f, 2.124f, 1.941f};
        const float bond [3] = {1.329f, 1.458f, 1.523f};
        #pragma unroll
        for (int k = 0; k < 3; ++k) {
            CA[k] = cosf(alpha[k]);
            SA[k] = sinf(alpha[k]);
            BOND[k] = bond[k];
        }
    }

    const float* pp = prev + (size_t)(Bbase + tid) * 9;
    float ax = pp[0], ay = pp[1], az = pp[2];
    float bx = pp[3], by = pp[4], bz = pp[5];
    float px = pp[6], py = pp[7], pz = pp[8];

    const float* gang = angles + (size_t)Bbase * (2 * NRES);
    float*       gout = out    + (size_t)Bbase * (NRES * 3);

    const float* ms = &s_sin[tid * SIN_PITCH];
    const float* mc = &s_cos[tid * SIN_PITCH];
    float*       mo = &s_out[tid * OUT_PITCH];

    float vx = 0.f, vy = 0.f, vz = 0.f;
    float wx = 0.f, wy = 0.f, wz = 0.f;

    #pragma unroll 1
    for (int ch = 0; ch < NCHUNK; ++ch) {
        const int i0 = ch * CHUNK;

        // ---- cooperative coalesced load of sin/cos tiles ----
        #pragma unroll
        for (int e = tid; e < TPB * CHUNK; e += TPB) {
            int r = e / CHUNK;
            int q = e - r * CHUNK;
            s_sin[r * SIN_PITCH + q] = gang[r * (2 * NRES) + i0 + q];
            s_cos[r * SIN_PITCH + q] = gang[r * (2 * NRES) + NRES + i0 + q];
        }
        __syncthreads();

        #define STEP(j) do {                                                       \
            const int k_ = (j) % 3;                                                \
            float s  = ms[(j)];                                                    \
            float co = mc[(j)];                                                    \
            float invn = frsqrt(fmaf(s, s, fmaf(co, co, 1e-8f)));                  \
            float t  = SA[k_] * invn;                                              \
            float r1 = t * co;                                                     \
            float r2 = -t * s;                                                     \
            float cxx = wy * vz - wz * vy;                                         \
            float cxy = wz * vx - wx * vz;                                         \
            float cxz = wx * vy - wy * vx;                                         \
            float inr = frsqrt(fmaf(cxx, cxx, fmaf(cxy, cxy,                        \
                                    fmaf(cxz, cxz, 1e-20f))));                     \
            float nx = cxx * inr, ny = cxy * inr, nz = cxz * inr;                  \
            float mx = wy * nz - wz * ny;                                          \
            float my = wz * nx - wx * nz;                                          \
            float mz = wx * ny - wy * nx;                                          \
            float ux = fmaf(-CA[k_], wx, fmaf(r1, mx, r2 * nx));                   \
            float uy = fmaf(-CA[k_], wy, fmaf(r1, my, r2 * ny));                   \
            float uz = fmaf(-CA[k_], wz, fmaf(r1, mz, r2 * nz));                   \
            px = fmaf(BOND[k_], ux, px);                                           \
            py = fmaf(BOND[k_], uy, py);                                           \
            pz = fmaf(BOND[k_], uz, pz);                                           \
            mo[(j) * 3 + 0] = px;                                                  \
            mo[(j) * 3 + 1] = py;                                                  \
            mo[(j) * 3 + 2] = pz;                                                  \
            float iun = frsqrt(fmaf(ux, ux, fmaf(uy, uy, uz * uz)));               \
            vx = wx; vy = wy; vz = wz;                                             \
            wx = ux * iun; wy = uy * iun; wz = uz * iun;                           \
        } while (0)

        if (ch == 0) {
            // ---- peeled step 0: reference-faithful on raw input geometry ----
            {
                float s  = ms[0];
                float co = mc[0];
                float invn = frsqrt(fmaf(s, s, fmaf(co, co, 1e-8f)));
                float t  = SA[0] * invn;
                float r1 = t * co;
                float r2 = -t * s;

                float bcx = (bx - px) + 1e-8f;
                float bcy = (by - py) + 1e-8f;
                float bcz = (bz - pz) + 1e-8f;
                float ib  = frsqrt(fmaf(bcx, bcx, fmaf(bcy, bcy, bcz * bcz)));
                bcx *= ib; bcy *= ib; bcz *= ib;

                float qx = bx - ax, qy = by - ay, qz = bz - az;
                float nx = fmaf(qy, bcz, fmaf(-qz, bcy, 1e-8f));
                float ny = fmaf(qz, bcx, fmaf(-qx, bcz, 1e-8f));
                float nz = fmaf(qx, bcy, fmaf(-qy, bcx, 1e-8f));
                float in_ = frsqrt(fmaf(nx, nx, fmaf(ny, ny, nz * nz)));
                nx *= in_; ny *= in_; nz *= in_;

                float mx = ny * bcz - nz * bcy;
                float my = nz * bcx - nx * bcz;
                float mz = nx * bcy - ny * bcx;

                float ux = fmaf(CA[0], bcx, fmaf(r1, mx, r2 * nx));
                float uy = fmaf(CA[0], bcy, fmaf(r1, my, r2 * ny));
                float uz = fmaf(CA[0], bcz, fmaf(r1, mz, r2 * nz));

                px = fmaf(BOND[0], ux, px);
                py = fmaf(BOND[0], uy, py);
                pz = fmaf(BOND[0], uz, pz);
                mo[0] = px; mo[1] = py; mo[2] = pz;

                float iun = frsqrt(fmaf(ux, ux, fmaf(uy, uy, uz * uz)));
                vx = -bcx; vy = -bcy; vz = -bcz;   // unit(c0 - b0)
                wx = ux * iun; wy = uy * iun; wz = uz * iun;
            }
            STEP(1); STEP(2); STEP(3); STEP(4);
            STEP(5); STEP(6); STEP(7); STEP(8);
        } else {
            STEP(0); STEP(1); STEP(2); STEP(3); STEP(4);
            STEP(5); STEP(6); STEP(7); STEP(8);
        }
        #undef STEP

        __syncthreads();

        // ---- cooperative coalesced store of output tile ----
        #pragma unroll
        for (int e = tid; e < TPB * CHUNK * 3; e += TPB) {
            int r = e / (CHUNK * 3);
            int q = e - r * (CHUNK * 3);
            gout[r * (NRES * 3) + i0 * 3 + q] = s_out[r * OUT_PITCH + q];
        }
        __syncthreads();
    }
}

extern "C" void kernel_launch(void* const* d_in, const int* in_sizes, int n_in,
                              void* d_out, int out_size)
{
    const float* angles = (const float*)d_in[0];   // (B, 252) f32
    const float* prev   = (const float*)d_in[1];   // (B, 3, 3) f32
    float*       out    = (float*)d_out;           // (B, 126, 3) f32

    const int B = in_sizes[0] / (2 * NRES);        // 65536
    dihedral_kernel<<<B / TPB, TPB>>>(angles, prev, out);
}

// round 5
// speedup vs baseline: 1.3793x; 1.1190x over previous
#include <cuda_runtime.h>

// DihedralToCartesian R5: segmented rigid-transform parallelization.
// Each chain (126 steps) split into SEG=6 segments of LSEG=21 steps.
// Segment s>=1 starts from a canonical frame (entry geometry is constant:
// u_{i-1}.u_{i-2} = -cos(alpha[2]) at boundaries i0 % 3 == 0), runs locally,
// then a short per-chain compose phase chains the rigid transforms, and each
// thread rotates its local points into global coordinates.
// TLP: 65536 chains * 6 segments = 393216 threads (vs 65536 before).

#define TPB    96
#define NRES   126
#define CHAINS 16              // chains per CTA
#define SEG    6               // segments per chain
#define LSEG   21              // steps per segment (21 % 3 == 0)

__device__ __forceinline__ float frsqrt(float x) {
    float y;
    asm("rsqrt.approx.f32 %0, %1;" : "=f"(y) : "f"(x));
    return y;
}

__global__ void __launch_bounds__(TPB, 7)
dihedral_kernel(const float* __restrict__ angles,
                const float* __restrict__ prev,
                float* __restrict__ out)
{
    // buf: per (chain,step) 3-float record. Holds sin/cos on load, then local
    // points (phase 1, in-place), then global points (phase 3, in-place).
    __shared__ float buf[CHAINS * NRES * 3];          // 24192 B
    __shared__ float ex [CHAINS * SEG * 9];           // q_last, w_f, v_f
    __shared__ float rp [CHAINS * SEG * 12];          // g1,g2,g3 (R columns), p

    const int tid   = threadIdx.x;
    const int c     = tid / SEG;
    const int s     = tid - c * SEG;
    const int Bbase = blockIdx.x * CHAINS;

    float CA[3], SA[3], BOND[3];
    {
        const float alpha[3] = {2.028f, 2.124f, 1.941f};
        const float bond [3] = {1.329f, 1.458f, 1.523f};
        #pragma unroll
        for (int k = 0; k < 3; ++k) {
            CA[k] = cosf(alpha[k]);
            SA[k] = sinf(alpha[k]);
            BOND[k] = bond[k];
        }
    }

    // ---- phase 0: coalesced load of sin/cos into buf records ----
    const float* gang = angles + (size_t)Bbase * (2 * NRES);
    #pragma unroll
    for (int i = 0; i < (CHAINS * NRES) / TPB; ++i) {   // 21 iters
        int e  = tid + i * TPB;
        int cc = e / NRES;
        int j  = e - cc * NRES;
        buf[e * 3 + 0] = gang[cc * (2 * NRES) + j];          // sin
        buf[e * 3 + 1] = gang[cc * (2 * NRES) + NRES + j];   // cos
    }
    __syncthreads();

    // ---- phase 1: run LSEG steps locally ----
    float* rec = &buf[(c * NRES + s * LSEG) * 3];
    float px, py, pz, vx, vy, vz, wx, wy, wz;

    #define STEP(j, K) do {                                                     \
        float s_ = rec[(j) * 3 + 0], co = rec[(j) * 3 + 1];                     \
        float invn = frsqrt(fmaf(s_, s_, fmaf(co, co, 1e-8f)));                 \
        float t  = SA[K] * invn;                                                \
        float r1 =  t * co;                                                     \
        float r2 = -t * s_;                                                     \
        float cxx = wy * vz - wz * vy;                                          \
        float cxy = wz * vx - wx * vz;                                          \
        float cxz = wx * vy - wy * vx;                                          \
        float inr = frsqrt(fmaf(cxx, cxx, fmaf(cxy, cxy,                        \
                                fmaf(cxz, cxz, 1e-20f))));                      \
        float nx = cxx * inr, ny = cxy * inr, nz = cxz * inr;                   \
        float mx = wy * nz - wz * ny;                                           \
        float my = wz * nx - wx * nz;                                           \
        float mz = wx * ny - wy * nx;                                           \
        float ux = fmaf(-CA[K], wx, fmaf(r1, mx, r2 * nx));                     \
        float uy = fmaf(-CA[K], wy, fmaf(r1, my, r2 * ny));                     \
        float uz = fmaf(-CA[K], wz, fmaf(r1, mz, r2 * nz));                     \
        px = fmaf(BOND[K], ux, px);                                             \
        py = fmaf(BOND[K], uy, py);                                             \
        pz = fmaf(BOND[K], uz, pz);                                             \
        rec[(j) * 3 + 0] = px;                                                  \
        rec[(j) * 3 + 1] = py;                                                  \
        rec[(j) * 3 + 2] = pz;                                                  \
        float iun = frsqrt(fmaf(ux, ux, fmaf(uy, uy, uz * uz)));                \
        vx = wx; vy = wy; vz = wz;                                              \
        wx = ux * iun; wy = uy * iun; wz = uz * iun;                            \
    } while (0)

    if (s == 0) {
        // segment 0: real geometry from prev_three, reference-faithful step 0
        const float* pp = prev + (size_t)(Bbase + c) * 9;
        float ax = pp[0], ay = pp[1], az = pp[2];
        float bx = pp[3], by = pp[4], bz = pp[5];
        px = pp[6]; py = pp[7]; pz = pp[8];

        float s_ = rec[0], co = rec[1];
        float invn = frsqrt(fmaf(s_, s_, fmaf(co, co, 1e-8f)));
        float t = SA[0] * invn, r1 = t * co, r2 = -t * s_;

        float bcx = (bx - px) + 1e-8f;
        float bcy = (by - py) + 1e-8f;
        float bcz = (bz - pz) + 1e-8f;
        float ib = frsqrt(fmaf(bcx, bcx, fmaf(bcy, bcy, bcz * bcz)));
        bcx *= ib; bcy *= ib; bcz *= ib;

        float qx = bx - ax, qy = by - ay, qz = bz - az;
        float nx = fmaf(qy, bcz, fmaf(-qz, bcy, 1e-8f));
        float ny = fmaf(qz, bcx, fmaf(-qx, bcz, 1e-8f));
        float nz = fmaf(qx, bcy, fmaf(-qy, bcx, 1e-8f));
        float in_ = frsqrt(fmaf(nx, nx, fmaf(ny, ny, nz * nz)));
        nx *= in_; ny *= in_; nz *= in_;

        float mx = ny * bcz - nz * bcy;
        float my = nz * bcx - nx * bcz;
        float mz = nx * bcy - ny * bcx;

        float ux = fmaf(CA[0], bcx, fmaf(r1, mx, r2 * nx));
        float uy = fmaf(CA[0], bcy, fmaf(r1, my, r2 * ny));
        float uz = fmaf(CA[0], bcz, fmaf(r1, mz, r2 * nz));

        px = fmaf(BOND[0], ux, px);
        py = fmaf(BOND[0], uy, py);
        pz = fmaf(BOND[0], uz, pz);
        rec[0] = px; rec[1] = py; rec[2] = pz;

        float iun = frsqrt(fmaf(ux, ux, fmaf(uy, uy, uz * uz)));
        vx = -bcx; vy = -bcy; vz = -bcz;   // unit(c0 - b0)
        wx = ux * iun; wy = uy * iun; wz = uz * iun;
    } else {
        // canonical entry frame: w0 = e1, v0 = -CA[2]*e1 + SA[2]*e2, p = 0
        px = 0.f; py = 0.f; pz = 0.f;
        wx = 1.f; wy = 0.f; wz = 0.f;
        vx = -CA[2]; vy = SA[2]; vz = 0.f;
        STEP(0, 0);
    }
    STEP(1, 1); STEP(2, 2);
    #pragma unroll
    for (int m = 1; m < 7; ++m) {
        STEP(3 * m + 0, 0);
        STEP(3 * m + 1, 1);
        STEP(3 * m + 2, 2);
    }
    #undef STEP

    {   // publish segment exit: last point, final w, final v (local coords)
        float* e9 = &ex[(c * SEG + s) * 9];
        e9[0] = px; e9[1] = py; e9[2] = pz;
        e9[3] = wx; e9[4] = wy; e9[5] = wz;
        e9[6] = vx; e9[7] = vy; e9[8] = vz;
    }
    __syncthreads();

    // ---- phase 2: per-chain sequential compose (16 lanes of warp 0) ----
    if (tid < CHAINS) {
        const int cc = tid;
        float* r0 = &rp[cc * SEG * 12];
        r0[0] = 1.f; r0[1] = 0.f; r0[2] = 0.f;     // segment 0: identity, origin
        r0[3] = 0.f; r0[4] = 1.f; r0[5] = 0.f;
        r0[6] = 0.f; r0[7] = 0.f; r0[8] = 1.f;
        r0[9] = 0.f; r0[10] = 0.f; r0[11] = 0.f;

        const float* e0 = &ex[cc * SEG * 9];
        float pex = e0[0], pey = e0[1], pez = e0[2];
        float wex = e0[3], wey = e0[4], wez = e0[5];
        float vex = e0[6], vey = e0[7], vez = e0[8];

        #pragma unroll
        for (int ss = 1; ss < SEG; ++ss) {
            // Gram-Schmidt basis from entry (w, v): g1 = w, g2 = unit(v_perp), g3 = g1 x g2
            float d  = fmaf(vex, wex, fmaf(vey, wey, vez * wez));
            float tx = fmaf(-d, wex, vex);
            float ty = fmaf(-d, wey, vey);
            float tz = fmaf(-d, wez, vez);
            float it = frsqrt(fmaf(tx, tx, fmaf(ty, ty, fmaf(tz, tz, 1e-20f))));
            float g1x = wex,     g1y = wey,     g1z = wez;
            float g2x = tx * it, g2y = ty * it, g2z = tz * it;
            float g3x = g1y * g2z - g1z * g2y;
            float g3y = g1z * g2x - g1x * g2z;
            float g3z = g1x * g2y - g1y * g2x;

            float* rr = &rp[(cc * SEG + ss) * 12];
            rr[0] = g1x; rr[1] = g1y; rr[2] = g1z;
            rr[3] = g2x; rr[4] = g2y; rr[5] = g2z;
            rr[6] = g3x; rr[7] = g3y; rr[8] = g3z;
            rr[9] = pex; rr[10] = pey; rr[11] = pez;

            // chain exit -> next entry (R applied to local exit state)
            const float* es = &ex[(cc * SEG + ss) * 9];
            float qx = es[0], qy = es[1], qz = es[2];
            float wfx = es[3], wfy = es[4], wfz = es[5];
            float vfx = es[6], vfy = es[7], vfz = es[8];

            float npx = pex + qx * g1x + qy * g2x + qz * g3x;
            float npy = pey + qx * g1y + qy * g2y + qz * g3y;
            float npz = pez + qx * g1z + qy * g2z + qz * g3z;
            wex = wfx * g1x + wfy * g2x + wfz * g3x;
            wey = wfx * g1y + wfy * g2y + wfz * g3y;
            wez = wfx * g1z + wfy * g2z + wfz * g3z;
            vex = vfx * g1x + vfy * g2x + vfz * g3x;
            vey = vfx * g1y + vfy * g2y + vfz * g3y;
            vez = vfx * g1z + vfy * g2z + vfz * g3z;
            pex = npx; pey = npy; pez = npz;
        }
    }
    __syncthreads();

    // ---- phase 3: rotate local points into global coords (in place) ----
    {
        const float* rr = &rp[(c * SEG + s) * 12];
        float g1x = rr[0], g1y = rr[1], g1z = rr[2];
        float g2x = rr[3], g2y = rr[4], g2z = rr[5];
        float g3x = rr[6], g3y = rr[7], g3z = rr[8];
        float ppx = rr[9], ppy = rr[10], ppz = rr[11];
        #pragma unroll 3
        for (int j = 0; j < LSEG; ++j) {
            float qx = rec[j * 3 + 0];
            float qy = rec[j * 3 + 1];
            float qz = rec[j * 3 + 2];
            rec[j * 3 + 0] = fmaf(qx, g1x, fmaf(qy, g2x, fmaf(qz, g3x, ppx)));
            rec[j * 3 + 1] = fmaf(qx, g1y, fmaf(qy, g2y, fmaf(qz, g3y, ppy)));
            rec[j * 3 + 2] = fmaf(qx, g1z, fmaf(qy, g2z, fmaf(qz, g3z, ppz)));
        }
    }
    __syncthreads();

    // ---- phase 4: flat coalesced store (buf layout == global layout) ----
    float* gout = out + (size_t)Bbase * (NRES * 3);
    #pragma unroll
    for (int i = 0; i < (CHAINS * NRES * 3) / TPB; ++i)   // 63 iters
        gout[tid + i * TPB] = buf[tid + i * TPB];
}

extern "C" void kernel_launch(void* const* d_in, const int* in_sizes, int n_in,
                              void* d_out, int out_size)
{
    const float* angles = (const float*)d_in[0];   // (B, 252) f32
    const float* prev   = (const float*)d_in[1];   // (B, 3, 3) f32
    float*       out    = (float*)d_out;           // (B, 126, 3) f32

    const int B = in_sizes[0] / (2 * NRES);        // 65536
    dihedral_kernel<<<B / CHAINS, TPB>>>(angles, prev, out);
}